// round 2
// baseline (speedup 1.0000x reference)
#include <cuda_runtime.h>
#include <cstdint>

#define DD 64
#define MAXN 50000

// scratch (static __device__ — no allocations allowed)
__device__ float g_agg[MAXN * DD];
__device__ float g_P[MAXN * DD];
__device__ float g_Q[MAXN * DD];   // holds emb@W1b + b1 (bias folded in)
__device__ int   g_is64;

// ---------------------------------------------------------------------------
// packed f32x2 helpers (Blackwell FFMA2 — only reachable via PTX)
// ---------------------------------------------------------------------------
__device__ __forceinline__ unsigned long long pack2s(float a) {
    unsigned long long r;
    asm("mov.b64 %0, {%1, %1};" : "=l"(r) : "f"(a));
    return r;
}
__device__ __forceinline__ unsigned long long pack2(float lo, float hi) {
    unsigned long long r;
    asm("mov.b64 %0, {%1, %2};" : "=l"(r) : "f"(lo), "f"(hi));
    return r;
}
__device__ __forceinline__ void unpack2(unsigned long long v, float& lo, float& hi) {
    asm("mov.b64 {%0, %1}, %2;" : "=f"(lo), "=f"(hi) : "l"(v));
}
__device__ __forceinline__ void fma2(unsigned long long& acc, unsigned long long a,
                                     unsigned long long b) {
    asm("fma.rn.f32x2 %0, %1, %2, %0;" : "+l"(acc) : "l"(a), "l"(b));
}

// ---------------------------------------------------------------------------
// Probe: edge_index may be int64 or int32 (JAX x64-off demotes silently).
// int64 with idx<50000 -> every odd 32-bit word is 0.
// ---------------------------------------------------------------------------
__global__ void k_detect(const int* __restrict__ ei) {
    if (threadIdx.x == 0 && blockIdx.x == 0) {
        int z = 0;
#pragma unroll
        for (int k = 1; k < 32; k += 2) z |= ei[k];
        g_is64 = (z == 0) ? 1 : 0;
    }
}

__device__ __forceinline__ long long edge_at(const void* ei, long long i, int is64) {
    if (is64) return ((const long long*)ei)[i];
    return (long long)((const int*)ei)[i];
}

// ---------------------------------------------------------------------------
__global__ void k_zero(int n4) {
    int i = blockIdx.x * blockDim.x + threadIdx.x;
    if (i < n4) ((float4*)g_agg)[i] = make_float4(0.f, 0.f, 0.f, 0.f);
}

// ---------------------------------------------------------------------------
// Scatter: agg[dst] += x[src]. 2 edges/warp, float4 lanes (16 lanes per row).
// ---------------------------------------------------------------------------
__global__ void k_scatter(const float* __restrict__ x, const void* __restrict__ ei, int E) {
    int is64 = g_is64;
    int t = blockIdx.x * blockDim.x + threadIdx.x;
    int warp = t >> 5;
    int lane = t & 31;
    long long e = (long long)warp * 2 + (lane >> 4);
    int sub = lane & 15;
    if (e >= E) return;
    long long src = edge_at(ei, e, is64);
    long long dst = edge_at(ei, (long long)E + e, is64);
    float4 v = ((const float4*)x)[src * 16 + sub];
    atomicAdd(((float4*)g_agg) + (dst * 16 + sub), v);
}

// ---------------------------------------------------------------------------
// Node kernel (thread per node, FFMA2):
//   in   = x[n] + agg[n]
//   emb  = relu(in @ W_enc + b_enc)
//   P[n] = emb @ W1a
//   Q[n] = emb @ W1b + b1          (b1 folded here, not per-edge)
// ONE 4096-float weight buffer, reloaded per phase -> 50KB smem -> 4 blocks/SM.
// Per-thread vector lives in padded smem (stride 65, conflict-free).
// Accumulators are 32 packed f32x2 pairs -> 64 regs, fma.rn.f32x2 inner loop.
// ---------------------------------------------------------------------------
#define NODE_TPB 128
#define SIN_STRIDE 65
#define NODE_SMEM_FLOATS (4096 + 128 + NODE_TPB * SIN_STRIDE)

__global__ void __launch_bounds__(NODE_TPB)
k_node(const float* __restrict__ x, const float* __restrict__ Wenc,
       const float* __restrict__ benc, const float* __restrict__ W1,
       const float* __restrict__ b1, int N) {
    extern __shared__ float sm[];
    float* sW  = sm;            // 4096 (phased: Wenc -> W1a -> W1b)
    float* sBe = sm + 4096;     // 64
    float* sB1 = sm + 4160;     // 64
    float* sIn = sm + 4224;     // NODE_TPB*65

    int tid = threadIdx.x;
    if (tid < 64) { sBe[tid] = benc[tid]; sB1[tid] = b1[tid]; }
    for (int i = tid; i < 4096; i += NODE_TPB) sW[i] = Wenc[i];

    int node = blockIdx.x * NODE_TPB + tid;
    bool act = node < N;
    int toff = tid * SIN_STRIDE;

    if (act) {
        const float4* x4 = (const float4*)x;
        const float4* a4 = (const float4*)g_agg;
#pragma unroll
        for (int c = 0; c < 16; c++) {
            float4 xv = x4[(long long)node * 16 + c];
            float4 av = a4[(long long)node * 16 + c];
            sIn[toff + 4 * c + 0] = xv.x + av.x;
            sIn[toff + 4 * c + 1] = xv.y + av.y;
            sIn[toff + 4 * c + 2] = xv.z + av.z;
            sIn[toff + 4 * c + 3] = xv.w + av.w;
        }
    } else {
        // keep slot finite so later math can't produce traps on garbage
#pragma unroll
        for (int c = 0; c < 64; c++) sIn[toff + c] = 0.f;
    }
    __syncthreads();

    unsigned long long acc[32];

    // ---- phase 1: emb = relu(in @ W_enc + b_enc) ----
#pragma unroll
    for (int j = 0; j < 32; j++) acc[j] = 0ULL;
#pragma unroll 8
    for (int k = 0; k < 64; k++) {
        unsigned long long aa = pack2s(sIn[toff + k]);
        const ulonglong2* w = (const ulonglong2*)(sW + k * 64);
#pragma unroll
        for (int j = 0; j < 16; j++) {
            ulonglong2 wv = w[j];
            fma2(acc[2 * j + 0], aa, wv.x);
            fma2(acc[2 * j + 1], aa, wv.y);
        }
    }
    __syncthreads();               // everyone done reading sW (=Wenc)
    for (int i = tid; i < 4096; i += NODE_TPB) sW[i] = W1[i];
#pragma unroll
    for (int j = 0; j < 32; j++) {
        float lo, hi;
        unpack2(acc[j], lo, hi);
        sIn[toff + 2 * j + 0] = fmaxf(lo + sBe[2 * j + 0], 0.f);
        sIn[toff + 2 * j + 1] = fmaxf(hi + sBe[2 * j + 1], 0.f);
    }
    __syncthreads();               // sW now W1a, own sIn slot rewritten

    // ---- phase 2: P = emb @ W1a ----
#pragma unroll
    for (int j = 0; j < 32; j++) acc[j] = 0ULL;
#pragma unroll 8
    for (int k = 0; k < 64; k++) {
        unsigned long long aa = pack2s(sIn[toff + k]);
        const ulonglong2* w = (const ulonglong2*)(sW + k * 64);
#pragma unroll
        for (int j = 0; j < 16; j++) {
            ulonglong2 wv = w[j];
            fma2(acc[2 * j + 0], aa, wv.x);
            fma2(acc[2 * j + 1], aa, wv.y);
        }
    }
    __syncthreads();               // done reading sW (=W1a)
    for (int i = tid; i < 4096; i += NODE_TPB) sW[i] = W1[4096 + i];
    if (act) {
        unsigned long long* P8 = (unsigned long long*)g_P;
#pragma unroll
        for (int j = 0; j < 32; j++) P8[(long long)node * 32 + j] = acc[j];
    }
    __syncthreads();               // sW now W1b

    // ---- phase 3: Q = emb @ W1b + b1 ----
#pragma unroll
    for (int j = 0; j < 32; j++) acc[j] = 0ULL;
#pragma unroll 8
    for (int k = 0; k < 64; k++) {
        unsigned long long aa = pack2s(sIn[toff + k]);
        const ulonglong2* w = (const ulonglong2*)(sW + k * 64);
#pragma unroll
        for (int j = 0; j < 16; j++) {
            ulonglong2 wv = w[j];
            fma2(acc[2 * j + 0], aa, wv.x);
            fma2(acc[2 * j + 1], aa, wv.y);
        }
    }
    if (act) {
        unsigned long long* Q8 = (unsigned long long*)g_Q;
#pragma unroll
        for (int j = 0; j < 32; j++) {
            float lo, hi;
            unpack2(acc[j], lo, hi);
            Q8[(long long)node * 32 + j] =
                pack2(lo + sB1[2 * j + 0], hi + sB1[2 * j + 1]);
        }
    }
}

// ---------------------------------------------------------------------------
// Edge kernel: 2 edges/warp, 16 float4-lanes per edge.
//   out[e] = relu(P[src] + Q[dst]) . W2 + b2      (b1 already in Q)
// ---------------------------------------------------------------------------
__global__ void k_edge(const void* __restrict__ ei, const float* __restrict__ W2,
                       const float* __restrict__ b2, float* __restrict__ out, int E) {
    int is64 = g_is64;
    int t = blockIdx.x * blockDim.x + threadIdx.x;
    int warp = t >> 5;
    int lane = t & 31;
    int half = lane >> 4;
    int sub  = lane & 15;
    long long e = (long long)warp * 2 + half;
    if (e >= E) return;

    long long src = edge_at(ei, e, is64);
    long long dst = edge_at(ei, (long long)E + e, is64);

    float4 p = ((const float4*)g_P)[src * 16 + sub];
    float4 q = ((const float4*)g_Q)[dst * 16 + sub];
    float4 w = __ldg(((const float4*)W2) + sub);

    float s = fmaxf(p.x + q.x, 0.f) * w.x
            + fmaxf(p.y + q.y, 0.f) * w.y
            + fmaxf(p.z + q.z, 0.f) * w.z
            + fmaxf(p.w + q.w, 0.f) * w.w;

    s += __shfl_xor_sync(0xFFFFFFFFu, s, 8);
    s += __shfl_xor_sync(0xFFFFFFFFu, s, 4);
    s += __shfl_xor_sync(0xFFFFFFFFu, s, 2);
    s += __shfl_xor_sync(0xFFFFFFFFu, s, 1);

    if (sub == 0) out[e] = s + __ldg(b2);
}

// ---------------------------------------------------------------------------
extern "C" void kernel_launch(void* const* d_in, const int* in_sizes, int n_in,
                              void* d_out, int out_size) {
    const float* x    = (const float*)d_in[0];
    const void*  ei   = d_in[1];
    const float* Wenc = (const float*)d_in[2];
    const float* benc = (const float*)d_in[3];
    const float* W1   = (const float*)d_in[4];
    const float* b1   = (const float*)d_in[5];
    const float* W2   = (const float*)d_in[6];
    const float* b2   = (const float*)d_in[7];
    float* out = (float*)d_out;

    int N = in_sizes[0] / DD;          // 50000
    int E = in_sizes[1] / 2;           // 800000

    k_detect<<<1, 32>>>((const int*)ei);

    int n4 = N * DD / 4;
    k_zero<<<(n4 + 255) / 256, 256>>>(n4);

    {
        long long warps = ((long long)E + 1) / 2;
        long long threads = warps * 32;
        int blocks = (int)((threads + 255) / 256);
        k_scatter<<<blocks, 256>>>(x, ei, E);
    }

    {
        int smem_bytes = NODE_SMEM_FLOATS * (int)sizeof(float);
        cudaFuncSetAttribute(k_node, cudaFuncAttributeMaxDynamicSharedMemorySize, smem_bytes);
        int blocks = (N + NODE_TPB - 1) / NODE_TPB;
        k_node<<<blocks, NODE_TPB, smem_bytes>>>(x, Wenc, benc, W1, b1, N);
    }

    {
        long long warps = ((long long)E + 1) / 2;
        long long threads = warps * 32;
        int blocks = (int)((threads + 255) / 256);
        k_edge<<<blocks, 256>>>(ei, W2, b2, out, E);
    }
}

// round 3
// speedup vs baseline: 1.1493x; 1.1493x over previous
#include <cuda_runtime.h>
#include <cstdint>

#define DD 64
#define MAXN 50000

// scratch (static __device__ — no allocations allowed)
__device__ float g_agg[MAXN * DD];
__device__ float g_P[MAXN * DD];
__device__ float g_Q[MAXN * DD];   // holds emb@W1b + b1 (bias folded in)
__device__ int   g_is64;

// ---------------------------------------------------------------------------
// edge_index may be int64 or int32 (JAX x64-off demotes silently).
// int64 with idx<50000 -> every odd 32-bit word is 0.
// ---------------------------------------------------------------------------
__device__ __forceinline__ long long edge_at(const void* ei, long long i, int is64) {
    if (is64) return ((const long long*)ei)[i];
    return (long long)((const int*)ei)[i];
}

// ---------------------------------------------------------------------------
// Zero agg + dtype probe (fused, saves a launch)
// ---------------------------------------------------------------------------
__global__ void k_zero(const int* __restrict__ ei, int n4) {
    int i = blockIdx.x * blockDim.x + threadIdx.x;
    if (i < n4) ((float4*)g_agg)[i] = make_float4(0.f, 0.f, 0.f, 0.f);
    if (i == 0) {
        int z = 0;
#pragma unroll
        for (int k = 1; k < 32; k += 2) z |= ei[k];
        g_is64 = (z == 0) ? 1 : 0;
    }
}

// ---------------------------------------------------------------------------
// Scatter: agg[dst] += x[src]. 2 edges/warp, float4 lanes (16 lanes per row).
// ---------------------------------------------------------------------------
__global__ void k_scatter(const float* __restrict__ x, const void* __restrict__ ei, int E) {
    int is64 = g_is64;
    int t = blockIdx.x * blockDim.x + threadIdx.x;
    int warp = t >> 5;
    int lane = t & 31;
    long long e = (long long)warp * 2 + (lane >> 4);
    int sub = lane & 15;
    if (e >= E) return;
    long long src = edge_at(ei, e, is64);
    long long dst = edge_at(ei, (long long)E + e, is64);
    float4 v = ((const float4*)x)[src * 16 + sub];
    atomicAdd(((float4*)g_agg) + (dst * 16 + sub), v);
}

// ---------------------------------------------------------------------------
// Node kernel: register-tiled chained GEMM.
// Block = TILE_M=32 nodes, 256 threads (tm 0..15: 2 nodes each; tn 0..15).
//   In^T staged in smem (transposed, stride 36)
//   phase1: emb = relu(In @ Wenc + be)        thread tile 2x4
//   phase2: [P|Q] = emb @ [W1a|W1b] (+b1->Q)  thread tile 2x8
// All weights resident in smem for the whole block (59KB -> 3 blocks/SM).
// A-operand via conflict-free float2 LDS, B via broadcast float4 LDS.
// ---------------------------------------------------------------------------
#define TILE_M 32
#define NODE_TPB 256
#define ST 36    // sInT row stride (floats), keeps float2/float4 alignment

// floats: sInT 64*36=2304 | sWe 4096 | sW1 8192 | sBe 64 | sB1 64
#define NODE_SMEM_FLOATS (2304 + 4096 + 8192 + 64 + 64)

__global__ void __launch_bounds__(NODE_TPB, 3)
k_node(const float* __restrict__ x, const float* __restrict__ Wenc,
       const float* __restrict__ benc, const float* __restrict__ W1,
       const float* __restrict__ b1, int N) {
    extern __shared__ float sm[];
    float* sInT = sm;            // 2304: [k 0..63][m 0..31] stride 36
    float* sWe  = sm + 2304;     // 4096: [k][64]
    float* sW1  = sm + 6400;     // 8192: [k][128]  (cols 0..63 = W1a, 64..127 = W1b)
    float* sBe  = sm + 14592;    // 64
    float* sB1  = sm + 14656;    // 64

    int tid = threadIdx.x;
    int node0 = blockIdx.x * TILE_M;

    // ---- stage weights ----
    for (int i = tid; i < 4096; i += NODE_TPB) sWe[i] = Wenc[i];
    for (int i = tid; i < 8192; i += NODE_TPB) {
        int part = i >> 12;
        int rem  = i & 4095;
        int k    = rem >> 6;
        int j    = rem & 63;
        sW1[k * 128 + part * 64 + j] = W1[i];
    }
    if (tid < 64) { sBe[tid] = benc[tid]; sB1[tid] = b1[tid]; }

    // ---- stage In^T = (x + agg)^T ----
    {
        const float4* x4 = (const float4*)x;
        const float4* a4 = (const float4*)g_agg;
#pragma unroll
        for (int it = 0; it < 2; it++) {
            int t = tid + it * NODE_TPB;
            int c = t & 15;          // float4 chunk (channel group)
            int r = t >> 4;          // local node 0..31
            int node = node0 + r;
            float4 s = make_float4(0.f, 0.f, 0.f, 0.f);
            if (node < N) {
                float4 xv = x4[(size_t)node * 16 + c];
                float4 av = a4[(size_t)node * 16 + c];
                s.x = xv.x + av.x; s.y = xv.y + av.y;
                s.z = xv.z + av.z; s.w = xv.w + av.w;
            }
            sInT[(4 * c + 0) * ST + r] = s.x;
            sInT[(4 * c + 1) * ST + r] = s.y;
            sInT[(4 * c + 2) * ST + r] = s.z;
            sInT[(4 * c + 3) * ST + r] = s.w;
        }
    }
    __syncthreads();

    int tm = tid & 15;     // node pair index
    int tn = tid >> 4;     // 0..15

    // ---- phase 1: emb = relu(In @ Wenc + be), tile 2x4 ----
    float c1[2][4];
#pragma unroll
    for (int i = 0; i < 4; i++) { c1[0][i] = 0.f; c1[1][i] = 0.f; }
#pragma unroll 16
    for (int k = 0; k < 64; k++) {
        float2 a = *(const float2*)&sInT[k * ST + 2 * tm];
        float4 b = *(const float4*)&sWe[k * 64 + 4 * tn];
        c1[0][0] += a.x * b.x; c1[0][1] += a.x * b.y;
        c1[0][2] += a.x * b.z; c1[0][3] += a.x * b.w;
        c1[1][0] += a.y * b.x; c1[1][1] += a.y * b.y;
        c1[1][2] += a.y * b.z; c1[1][3] += a.y * b.w;
    }
    __syncthreads();          // all sInT reads done
#pragma unroll
    for (int i = 0; i < 4; i++) {
        float bb = sBe[4 * tn + i];
        sInT[(4 * tn + i) * ST + 2 * tm]     = fmaxf(c1[0][i] + bb, 0.f);
        sInT[(4 * tn + i) * ST + 2 * tm + 1] = fmaxf(c1[1][i] + bb, 0.f);
    }
    __syncthreads();          // emb^T staged

    // ---- phase 2: [P|Q] = emb @ [W1a|W1b], tile 2x8 ----
    float c2[2][8];
#pragma unroll
    for (int i = 0; i < 8; i++) { c2[0][i] = 0.f; c2[1][i] = 0.f; }
#pragma unroll 8
    for (int k = 0; k < 64; k++) {
        float2 a  = *(const float2*)&sInT[k * ST + 2 * tm];
        float4 b0 = *(const float4*)&sW1[k * 128 + 8 * tn];
        float4 b1v = *(const float4*)&sW1[k * 128 + 8 * tn + 4];
        c2[0][0] += a.x * b0.x; c2[0][1] += a.x * b0.y;
        c2[0][2] += a.x * b0.z; c2[0][3] += a.x * b0.w;
        c2[0][4] += a.x * b1v.x; c2[0][5] += a.x * b1v.y;
        c2[0][6] += a.x * b1v.z; c2[0][7] += a.x * b1v.w;
        c2[1][0] += a.y * b0.x; c2[1][1] += a.y * b0.y;
        c2[1][2] += a.y * b0.z; c2[1][3] += a.y * b0.w;
        c2[1][4] += a.y * b1v.x; c2[1][5] += a.y * b1v.y;
        c2[1][6] += a.y * b1v.z; c2[1][7] += a.y * b1v.w;
    }

    // ---- epilogue: tn<8 -> P cols 8tn.., tn>=8 -> Q cols 8(tn-8).. (+b1) ----
#pragma unroll
    for (int r = 0; r < 2; r++) {
        int node = node0 + 2 * tm + r;
        if (node >= N) continue;
        if (tn < 8) {
            float4* dst = (float4*)(g_P + (size_t)node * 64 + 8 * tn);
            dst[0] = make_float4(c2[r][0], c2[r][1], c2[r][2], c2[r][3]);
            dst[1] = make_float4(c2[r][4], c2[r][5], c2[r][6], c2[r][7]);
        } else {
            int j = 8 * (tn - 8);
            float4* dst = (float4*)(g_Q + (size_t)node * 64 + j);
            dst[0] = make_float4(c2[r][0] + sB1[j + 0], c2[r][1] + sB1[j + 1],
                                 c2[r][2] + sB1[j + 2], c2[r][3] + sB1[j + 3]);
            dst[1] = make_float4(c2[r][4] + sB1[j + 4], c2[r][5] + sB1[j + 5],
                                 c2[r][6] + sB1[j + 6], c2[r][7] + sB1[j + 7]);
        }
    }
}

// ---------------------------------------------------------------------------
// Edge kernel: 2 edges/warp, 16 float4-lanes per edge.
//   out[e] = relu(P[src] + Q[dst]) . W2 + b2      (b1 already in Q)
// ---------------------------------------------------------------------------
__global__ void k_edge(const void* __restrict__ ei, const float* __restrict__ W2,
                       const float* __restrict__ b2, float* __restrict__ out, int E) {
    int is64 = g_is64;
    int t = blockIdx.x * blockDim.x + threadIdx.x;
    int warp = t >> 5;
    int lane = t & 31;
    int half = lane >> 4;
    int sub  = lane & 15;
    long long e = (long long)warp * 2 + half;
    if (e >= E) return;

    long long src = edge_at(ei, e, is64);
    long long dst = edge_at(ei, (long long)E + e, is64);

    float4 p = ((const float4*)g_P)[src * 16 + sub];
    float4 q = ((const float4*)g_Q)[dst * 16 + sub];
    float4 w = __ldg(((const float4*)W2) + sub);

    float s = fmaxf(p.x + q.x, 0.f) * w.x
            + fmaxf(p.y + q.y, 0.f) * w.y
            + fmaxf(p.z + q.z, 0.f) * w.z
            + fmaxf(p.w + q.w, 0.f) * w.w;

    s += __shfl_xor_sync(0xFFFFFFFFu, s, 8);
    s += __shfl_xor_sync(0xFFFFFFFFu, s, 4);
    s += __shfl_xor_sync(0xFFFFFFFFu, s, 2);
    s += __shfl_xor_sync(0xFFFFFFFFu, s, 1);

    if (sub == 0) out[e] = s + __ldg(b2);
}

// ---------------------------------------------------------------------------
extern "C" void kernel_launch(void* const* d_in, const int* in_sizes, int n_in,
                              void* d_out, int out_size) {
    const float* x    = (const float*)d_in[0];
    const void*  ei   = d_in[1];
    const float* Wenc = (const float*)d_in[2];
    const float* benc = (const float*)d_in[3];
    const float* W1   = (const float*)d_in[4];
    const float* b1   = (const float*)d_in[5];
    const float* W2   = (const float*)d_in[6];
    const float* b2   = (const float*)d_in[7];
    float* out = (float*)d_out;

    int N = in_sizes[0] / DD;          // 50000
    int E = in_sizes[1] / 2;           // 800000

    // zero agg + dtype probe
    int n4 = N * DD / 4;
    k_zero<<<(n4 + 255) / 256, 256>>>((const int*)ei, n4);

    // scatter-add x[src] into agg[dst]
    {
        long long warps = ((long long)E + 1) / 2;
        long long threads = warps * 32;
        int blocks = (int)((threads + 255) / 256);
        k_scatter<<<blocks, 256>>>(x, ei, E);
    }

    // node GEMMs (emb, P, Q) — register tiled
    {
        int smem_bytes = NODE_SMEM_FLOATS * (int)sizeof(float);
        cudaFuncSetAttribute(k_node, cudaFuncAttributeMaxDynamicSharedMemorySize, smem_bytes);
        int blocks = (N + TILE_M - 1) / TILE_M;
        k_node<<<blocks, NODE_TPB, smem_bytes>>>(x, Wenc, benc, W1, b1, N);
    }

    // per-edge MLP
    {
        long long warps = ((long long)E + 1) / 2;
        long long threads = warps * 32;
        int blocks = (int)((threads + 255) / 256);
        k_edge<<<blocks, 256>>>(ei, W2, b2, out, E);
    }
}

// round 4
// speedup vs baseline: 1.8142x; 1.5786x over previous
#include <cuda_runtime.h>
#include <cuda_fp16.h>
#include <cstdint>

#define DD 64
#define MAXN 50000

// scratch (static __device__ — no allocations allowed)
__device__ float  g_agg[MAXN * DD];
__device__ __half g_P[MAXN * DD];   // fp16 node_emb @ W1a
__device__ __half g_Q[MAXN * DD];   // fp16 node_emb @ W1b + b1 (bias folded)
__device__ int    g_shift;          // 0 = int32 edge_index, 1 = int64

// ---------------------------------------------------------------------------
// Zero agg + dtype probe (int64 with idx<50000 -> every odd 32-bit word == 0)
// ---------------------------------------------------------------------------
__global__ void k_zero(const int* __restrict__ ei, int n4) {
    int i = blockIdx.x * blockDim.x + threadIdx.x;
    if (i < n4) ((float4*)g_agg)[i] = make_float4(0.f, 0.f, 0.f, 0.f);
    if (i == 0) {
        int z = 0;
#pragma unroll
        for (int k = 1; k < 32; k += 2) z |= ei[k];
        g_shift = (z == 0) ? 1 : 0;
    }
}

// idx fits in 31 bits -> just read the low 32-bit word (little-endian)
__device__ __forceinline__ int eidx(const int* __restrict__ ei, int i, int shift) {
    return ei[(long long)i << shift];
}

// ---------------------------------------------------------------------------
// Scatter: agg[dst] += x[src]. 2 edges/warp, float4 lanes; int32 math.
// ---------------------------------------------------------------------------
__global__ void k_scatter(const float* __restrict__ x, const int* __restrict__ ei, int E) {
    int shift = g_shift;
    int t = blockIdx.x * blockDim.x + threadIdx.x;
    int warp = t >> 5;
    int lane = t & 31;
    int e = warp * 2 + (lane >> 4);
    int sub = lane & 15;
    if (e >= E) return;
    int src = eidx(ei, e, shift);
    int dst = eidx(ei, E + e, shift);
    float4 v = ((const float4*)x)[src * 16 + sub];
    atomicAdd(((float4*)g_agg) + (dst * 16 + sub), v);
}

// ---------------------------------------------------------------------------
// Node kernel: register-tiled chained GEMM (same as R3, fp16 epilogue).
// Block = 32 nodes, 256 threads.
//   phase1: emb = relu(In @ Wenc + be)        thread tile 2x4
//   phase2: [P|Q] = emb @ [W1a|W1b] (+b1->Q)  thread tile 2x8, store half
// ---------------------------------------------------------------------------
#define TILE_M 32
#define NODE_TPB 256
#define ST 36
#define NODE_SMEM_FLOATS (2304 + 4096 + 8192 + 64 + 64)

struct alignas(16) h8 { __half2 a, b, c, d; };

__global__ void __launch_bounds__(NODE_TPB, 3)
k_node(const float* __restrict__ x, const float* __restrict__ Wenc,
       const float* __restrict__ benc, const float* __restrict__ W1,
       const float* __restrict__ b1, int N) {
    extern __shared__ float sm[];
    float* sInT = sm;            // 2304: [k][m] stride 36
    float* sWe  = sm + 2304;     // 4096: [k][64]
    float* sW1  = sm + 6400;     // 8192: [k][128] (0..63 = W1a, 64..127 = W1b)
    float* sBe  = sm + 14592;    // 64
    float* sB1  = sm + 14656;    // 64

    int tid = threadIdx.x;
    int node0 = blockIdx.x * TILE_M;

    for (int i = tid; i < 4096; i += NODE_TPB) sWe[i] = Wenc[i];
    for (int i = tid; i < 8192; i += NODE_TPB) {
        int part = i >> 12;
        int rem  = i & 4095;
        int k    = rem >> 6;
        int j    = rem & 63;
        sW1[k * 128 + part * 64 + j] = W1[i];
    }
    if (tid < 64) { sBe[tid] = benc[tid]; sB1[tid] = b1[tid]; }

    {
        const float4* x4 = (const float4*)x;
        const float4* a4 = (const float4*)g_agg;
#pragma unroll
        for (int it = 0; it < 2; it++) {
            int t = tid + it * NODE_TPB;
            int c = t & 15;
            int r = t >> 4;
            int node = node0 + r;
            float4 s = make_float4(0.f, 0.f, 0.f, 0.f);
            if (node < N) {
                float4 xv = x4[(size_t)node * 16 + c];
                float4 av = a4[(size_t)node * 16 + c];
                s.x = xv.x + av.x; s.y = xv.y + av.y;
                s.z = xv.z + av.z; s.w = xv.w + av.w;
            }
            sInT[(4 * c + 0) * ST + r] = s.x;
            sInT[(4 * c + 1) * ST + r] = s.y;
            sInT[(4 * c + 2) * ST + r] = s.z;
            sInT[(4 * c + 3) * ST + r] = s.w;
        }
    }
    __syncthreads();

    int tm = tid & 15;
    int tn = tid >> 4;

    // ---- phase 1 ----
    float c1[2][4];
#pragma unroll
    for (int i = 0; i < 4; i++) { c1[0][i] = 0.f; c1[1][i] = 0.f; }
#pragma unroll 16
    for (int k = 0; k < 64; k++) {
        float2 a = *(const float2*)&sInT[k * ST + 2 * tm];
        float4 b = *(const float4*)&sWe[k * 64 + 4 * tn];
        c1[0][0] += a.x * b.x; c1[0][1] += a.x * b.y;
        c1[0][2] += a.x * b.z; c1[0][3] += a.x * b.w;
        c1[1][0] += a.y * b.x; c1[1][1] += a.y * b.y;
        c1[1][2] += a.y * b.z; c1[1][3] += a.y * b.w;
    }
    __syncthreads();
#pragma unroll
    for (int i = 0; i < 4; i++) {
        float bb = sBe[4 * tn + i];
        sInT[(4 * tn + i) * ST + 2 * tm]     = fmaxf(c1[0][i] + bb, 0.f);
        sInT[(4 * tn + i) * ST + 2 * tm + 1] = fmaxf(c1[1][i] + bb, 0.f);
    }
    __syncthreads();

    // ---- phase 2 ----
    float c2[2][8];
#pragma unroll
    for (int i = 0; i < 8; i++) { c2[0][i] = 0.f; c2[1][i] = 0.f; }
#pragma unroll 8
    for (int k = 0; k < 64; k++) {
        float2 a   = *(const float2*)&sInT[k * ST + 2 * tm];
        float4 b0  = *(const float4*)&sW1[k * 128 + 8 * tn];
        float4 b1v = *(const float4*)&sW1[k * 128 + 8 * tn + 4];
        c2[0][0] += a.x * b0.x;  c2[0][1] += a.x * b0.y;
        c2[0][2] += a.x * b0.z;  c2[0][3] += a.x * b0.w;
        c2[0][4] += a.x * b1v.x; c2[0][5] += a.x * b1v.y;
        c2[0][6] += a.x * b1v.z; c2[0][7] += a.x * b1v.w;
        c2[1][0] += a.y * b0.x;  c2[1][1] += a.y * b0.y;
        c2[1][2] += a.y * b0.z;  c2[1][3] += a.y * b0.w;
        c2[1][4] += a.y * b1v.x; c2[1][5] += a.y * b1v.y;
        c2[1][6] += a.y * b1v.z; c2[1][7] += a.y * b1v.w;
    }

    // ---- epilogue: fp16 pack; tn<8 -> P, tn>=8 -> Q (+b1) ----
#pragma unroll
    for (int r = 0; r < 2; r++) {
        int node = node0 + 2 * tm + r;
        if (node >= N) continue;
        if (tn < 8) {
            h8 v;
            v.a = __floats2half2_rn(c2[r][0], c2[r][1]);
            v.b = __floats2half2_rn(c2[r][2], c2[r][3]);
            v.c = __floats2half2_rn(c2[r][4], c2[r][5]);
            v.d = __floats2half2_rn(c2[r][6], c2[r][7]);
            *(h8*)(g_P + (size_t)node * 64 + 8 * tn) = v;
        } else {
            int j = 8 * (tn - 8);
            h8 v;
            v.a = __floats2half2_rn(c2[r][0] + sB1[j + 0], c2[r][1] + sB1[j + 1]);
            v.b = __floats2half2_rn(c2[r][2] + sB1[j + 2], c2[r][3] + sB1[j + 3]);
            v.c = __floats2half2_rn(c2[r][4] + sB1[j + 4], c2[r][5] + sB1[j + 5]);
            v.d = __floats2half2_rn(c2[r][6] + sB1[j + 6], c2[r][7] + sB1[j + 7]);
            *(h8*)(g_Q + (size_t)node * 64 + j) = v;
        }
    }
}

// ---------------------------------------------------------------------------
// Edge kernel: 4 edges/warp, 8 lanes/edge, fp16 rows (one 128B line per row).
//   out[e] = relu(P[src] + Q[dst]) . W2 + b2
// Lane cid owns channels [8cid, 8cid+8): one LDG.128 from P, one from Q.
// ---------------------------------------------------------------------------
__global__ void k_edge(const int* __restrict__ ei, const float* __restrict__ W2,
                       const float* __restrict__ b2, float* __restrict__ out, int E) {
    int shift = g_shift;
    int t = blockIdx.x * blockDim.x + threadIdx.x;
    int warp = t >> 5;
    int lane = t & 31;
    int esub = lane >> 3;      // 0..3
    int cid  = lane & 7;       // 0..7
    int e = warp * 4 + esub;
    if (e >= E) return;

    int src = eidx(ei, e, shift);
    int dst = eidx(ei, E + e, shift);

    const h8* Ph = (const h8*)g_P;
    const h8* Qh = (const h8*)g_Q;
    h8 p = Ph[src * 8 + cid];
    h8 q = Qh[dst * 8 + cid];

    float4 w0 = __ldg((const float4*)W2 + 2 * cid);
    float4 w1 = __ldg((const float4*)W2 + 2 * cid + 1);

    float2 p0 = __half22float2(p.a), p1 = __half22float2(p.b);
    float2 p2 = __half22float2(p.c), p3 = __half22float2(p.d);
    float2 q0 = __half22float2(q.a), q1 = __half22float2(q.b);
    float2 q2 = __half22float2(q.c), q3 = __half22float2(q.d);

    float s = fmaxf(p0.x + q0.x, 0.f) * w0.x
            + fmaxf(p0.y + q0.y, 0.f) * w0.y
            + fmaxf(p1.x + q1.x, 0.f) * w0.z
            + fmaxf(p1.y + q1.y, 0.f) * w0.w
            + fmaxf(p2.x + q2.x, 0.f) * w1.x
            + fmaxf(p2.y + q2.y, 0.f) * w1.y
            + fmaxf(p3.x + q3.x, 0.f) * w1.z
            + fmaxf(p3.y + q3.y, 0.f) * w1.w;

    s += __shfl_xor_sync(0xFFFFFFFFu, s, 4);
    s += __shfl_xor_sync(0xFFFFFFFFu, s, 2);
    s += __shfl_xor_sync(0xFFFFFFFFu, s, 1);

    if (cid == 0) out[e] = s + __ldg(b2);
}

// ---------------------------------------------------------------------------
extern "C" void kernel_launch(void* const* d_in, const int* in_sizes, int n_in,
                              void* d_out, int out_size) {
    const float* x    = (const float*)d_in[0];
    const int*   ei   = (const int*)d_in[1];
    const float* Wenc = (const float*)d_in[2];
    const float* benc = (const float*)d_in[3];
    const float* W1   = (const float*)d_in[4];
    const float* b1   = (const float*)d_in[5];
    const float* W2   = (const float*)d_in[6];
    const float* b2   = (const float*)d_in[7];
    float* out = (float*)d_out;

    int N = in_sizes[0] / DD;          // 50000
    int E = in_sizes[1] / 2;           // 800000

    int n4 = N * DD / 4;
    k_zero<<<(n4 + 255) / 256, 256>>>(ei, n4);

    {
        long long warps = ((long long)E + 1) / 2;
        long long threads = warps * 32;
        int blocks = (int)((threads + 255) / 256);
        k_scatter<<<blocks, 256>>>(x, ei, E);
    }

    {
        int smem_bytes = NODE_SMEM_FLOATS * (int)sizeof(float);
        cudaFuncSetAttribute(k_node, cudaFuncAttributeMaxDynamicSharedMemorySize, smem_bytes);
        int blocks = (N + TILE_M - 1) / TILE_M;
        k_node<<<blocks, NODE_TPB, smem_bytes>>>(x, Wenc, benc, W1, b1, N);
    }

    {
        long long warps = ((long long)E + 3) / 4;
        long long threads = warps * 32;
        int blocks = (int)((threads + 255) / 256);
        k_edge<<<blocks, 256>>>(ei, W2, b2, out, E);
    }
}

// round 5
// speedup vs baseline: 2.1398x; 1.1794x over previous
#include <cuda_runtime.h>
#include <cuda_fp16.h>
#include <cstdint>

#define DD 64
#define MAXN 50000

// scratch (static __device__ — no allocations allowed)
__device__ float  g_in[MAXN * DD];    // x pre-filled, scatter adds -> In = x + agg
__device__ __half g_xh[MAXN * DD];    // fp16 copy of x (scatter read source)
__device__ __half g_P[MAXN * DD];     // fp16 node_emb @ W1a
__device__ __half g_Q[MAXN * DD];     // fp16 node_emb @ W1b + b1 (bias folded)
__device__ int    g_shift;            // 0 = int32 edge_index, 1 = int64

struct alignas(16) h8 { __half2 a, b, c, d; };
struct alignas(8)  h4 { __half2 a, b; };

// ---------------------------------------------------------------------------
// Copy/convert + dtype probe: g_in = x; g_xh = half(x).
// (int64 with idx<50000 -> every odd 32-bit word == 0)
// ---------------------------------------------------------------------------
__global__ void k_prep(const float* __restrict__ x, const int* __restrict__ ei, int n4) {
    int i = blockIdx.x * blockDim.x + threadIdx.x;
    if (i < n4) {
        float4 v = ((const float4*)x)[i];
        ((float4*)g_in)[i] = v;
        h4 h;
        h.a = __floats2half2_rn(v.x, v.y);
        h.b = __floats2half2_rn(v.z, v.w);
        ((h4*)g_xh)[i] = h;
    }
    if (i == 0) {
        int z = 0;
#pragma unroll
        for (int k = 1; k < 32; k += 2) z |= ei[k];
        g_shift = (z == 0) ? 1 : 0;
    }
}

// idx fits in 31 bits -> read the low 32-bit word (little-endian)
__device__ __forceinline__ int eidx(const int* __restrict__ ei, long long i, int shift) {
    return ei[i << shift];
}

// ---------------------------------------------------------------------------
// Scatter: In[dst] += x[src]. 2 edges/warp, 16 lanes/edge.
// Reads fp16 row (8B/lane, streaming), atomics fp32 float4 (16B/lane).
// ---------------------------------------------------------------------------
__global__ void k_scatter(const int* __restrict__ ei, int E) {
    int shift = g_shift;
    int t = blockIdx.x * blockDim.x + threadIdx.x;
    int warp = t >> 5;
    int lane = t & 31;
    int e = warp * 2 + (lane >> 4);
    int sub = lane & 15;
    if (e >= E) return;
    int src = eidx(ei, e, shift);
    int dst = eidx(ei, (long long)E + e, shift);

    float2 raw = __ldcs((const float2*)(g_xh + (size_t)src * 64) + sub);
    h4 hv = *(h4*)&raw;
    float2 f0 = __half22float2(hv.a);
    float2 f1 = __half22float2(hv.b);
    atomicAdd((float4*)(g_in + (size_t)dst * 64) + sub,
              make_float4(f0.x, f0.y, f1.x, f1.y));
}

// ---------------------------------------------------------------------------
// Node kernel: register-tiled chained GEMM, fp16 epilogue.
// Block = 32 nodes, 256 threads.
//   phase1: emb = relu(In @ Wenc + be)        thread tile 2x4
//   phase2: [P|Q] = emb @ [W1a|W1b] (+b1->Q)  thread tile 2x8, store half
// ---------------------------------------------------------------------------
#define TILE_M 32
#define NODE_TPB 256
#define ST 36
#define NODE_SMEM_FLOATS (2304 + 4096 + 8192 + 64 + 64)

__global__ void __launch_bounds__(NODE_TPB, 3)
k_node(const float* __restrict__ Wenc, const float* __restrict__ benc,
       const float* __restrict__ W1, const float* __restrict__ b1, int N) {
    extern __shared__ float sm[];
    float* sInT = sm;            // 2304: [k][m] stride 36
    float* sWe  = sm + 2304;     // 4096: [k][64]
    float* sW1  = sm + 6400;     // 8192: [k][128] (0..63 = W1a, 64..127 = W1b)
    float* sBe  = sm + 14592;    // 64
    float* sB1  = sm + 14656;    // 64

    int tid = threadIdx.x;
    int node0 = blockIdx.x * TILE_M;

    for (int i = tid; i < 4096; i += NODE_TPB) sWe[i] = Wenc[i];
    for (int i = tid; i < 8192; i += NODE_TPB) {
        int part = i >> 12;
        int rem  = i & 4095;
        int k    = rem >> 6;
        int j    = rem & 63;
        sW1[k * 128 + part * 64 + j] = W1[i];
    }
    if (tid < 64) { sBe[tid] = benc[tid]; sB1[tid] = b1[tid]; }

    {
        const float4* in4 = (const float4*)g_in;
#pragma unroll
        for (int it = 0; it < 2; it++) {
            int t = tid + it * NODE_TPB;
            int c = t & 15;
            int r = t >> 4;
            int node = node0 + r;
            float4 s = make_float4(0.f, 0.f, 0.f, 0.f);
            if (node < N) s = in4[(size_t)node * 16 + c];
            sInT[(4 * c + 0) * ST + r] = s.x;
            sInT[(4 * c + 1) * ST + r] = s.y;
            sInT[(4 * c + 2) * ST + r] = s.z;
            sInT[(4 * c + 3) * ST + r] = s.w;
        }
    }
    __syncthreads();

    int tm = tid & 15;
    int tn = tid >> 4;

    // ---- phase 1 ----
    float c1[2][4];
#pragma unroll
    for (int i = 0; i < 4; i++) { c1[0][i] = 0.f; c1[1][i] = 0.f; }
#pragma unroll 16
    for (int k = 0; k < 64; k++) {
        float2 a = *(const float2*)&sInT[k * ST + 2 * tm];
        float4 b = *(const float4*)&sWe[k * 64 + 4 * tn];
        c1[0][0] += a.x * b.x; c1[0][1] += a.x * b.y;
        c1[0][2] += a.x * b.z; c1[0][3] += a.x * b.w;
        c1[1][0] += a.y * b.x; c1[1][1] += a.y * b.y;
        c1[1][2] += a.y * b.z; c1[1][3] += a.y * b.w;
    }
    __syncthreads();
#pragma unroll
    for (int i = 0; i < 4; i++) {
        float bb = sBe[4 * tn + i];
        sInT[(4 * tn + i) * ST + 2 * tm]     = fmaxf(c1[0][i] + bb, 0.f);
        sInT[(4 * tn + i) * ST + 2 * tm + 1] = fmaxf(c1[1][i] + bb, 0.f);
    }
    __syncthreads();

    // ---- phase 2 ----
    float c2[2][8];
#pragma unroll
    for (int i = 0; i < 8; i++) { c2[0][i] = 0.f; c2[1][i] = 0.f; }
#pragma unroll 8
    for (int k = 0; k < 64; k++) {
        float2 a   = *(const float2*)&sInT[k * ST + 2 * tm];
        float4 b0  = *(const float4*)&sW1[k * 128 + 8 * tn];
        float4 b1v = *(const float4*)&sW1[k * 128 + 8 * tn + 4];
        c2[0][0] += a.x * b0.x;  c2[0][1] += a.x * b0.y;
        c2[0][2] += a.x * b0.z;  c2[0][3] += a.x * b0.w;
        c2[0][4] += a.x * b1v.x; c2[0][5] += a.x * b1v.y;
        c2[0][6] += a.x * b1v.z; c2[0][7] += a.x * b1v.w;
        c2[1][0] += a.y * b0.x;  c2[1][1] += a.y * b0.y;
        c2[1][2] += a.y * b0.z;  c2[1][3] += a.y * b0.w;
        c2[1][4] += a.y * b1v.x; c2[1][5] += a.y * b1v.y;
        c2[1][6] += a.y * b1v.z; c2[1][7] += a.y * b1v.w;
    }

    // ---- epilogue ----
#pragma unroll
    for (int r = 0; r < 2; r++) {
        int node = node0 + 2 * tm + r;
        if (node >= N) continue;
        if (tn < 8) {
            h8 v;
            v.a = __floats2half2_rn(c2[r][0], c2[r][1]);
            v.b = __floats2half2_rn(c2[r][2], c2[r][3]);
            v.c = __floats2half2_rn(c2[r][4], c2[r][5]);
            v.d = __floats2half2_rn(c2[r][6], c2[r][7]);
            *(h8*)(g_P + (size_t)node * 64 + 8 * tn) = v;
        } else {
            int j = 8 * (tn - 8);
            h8 v;
            v.a = __floats2half2_rn(c2[r][0] + sB1[j + 0], c2[r][1] + sB1[j + 1]);
            v.b = __floats2half2_rn(c2[r][2] + sB1[j + 2], c2[r][3] + sB1[j + 3]);
            v.c = __floats2half2_rn(c2[r][4] + sB1[j + 4], c2[r][5] + sB1[j + 5]);
            v.d = __floats2half2_rn(c2[r][6] + sB1[j + 6], c2[r][7] + sB1[j + 7]);
            *(h8*)(g_Q + (size_t)node * 64 + j) = v;
        }
    }
}

// ---------------------------------------------------------------------------
// Edge kernel: 8 edges/warp (2 per 8-lane group), fp16 rows, streaming loads.
//   out[e] = relu(P[src] + Q[dst]) . W2 + b2
// 4 independent 16B gathers in flight per thread (MLP=4).
// ---------------------------------------------------------------------------
__global__ void k_edge(const int* __restrict__ ei, const float* __restrict__ W2,
                       const float* __restrict__ b2, float* __restrict__ out, int E) {
    int shift = g_shift;
    int t = blockIdx.x * blockDim.x + threadIdx.x;
    int warp = t >> 5;
    int lane = t & 31;
    int esub = lane >> 3;      // 0..3
    int cid  = lane & 7;       // 0..7
    long long e0 = (long long)warp * 8 + esub;
    long long e1 = e0 + 4;
    bool v0 = e0 < E, v1 = e1 < E;

    int s0 = v0 ? eidx(ei, e0, shift) : 0;
    int d0 = v0 ? eidx(ei, (long long)E + e0, shift) : 0;
    int s1 = v1 ? eidx(ei, e1, shift) : 0;
    int d1 = v1 ? eidx(ei, (long long)E + e1, shift) : 0;

    const float4* Pf = (const float4*)g_P;
    const float4* Qf = (const float4*)g_Q;
    float4 pr0 = __ldcs(Pf + (size_t)s0 * 8 + cid);
    float4 qr0 = __ldcs(Qf + (size_t)d0 * 8 + cid);
    float4 pr1 = __ldcs(Pf + (size_t)s1 * 8 + cid);
    float4 qr1 = __ldcs(Qf + (size_t)d1 * 8 + cid);

    float4 w0 = __ldg((const float4*)W2 + 2 * cid);
    float4 w1 = __ldg((const float4*)W2 + 2 * cid + 1);
    float bias = __ldg(b2);
    const __half2 hz = __float2half2_rn(0.f);

    h8 p0 = *(h8*)&pr0, q0 = *(h8*)&qr0;
    h8 p1 = *(h8*)&pr1, q1 = *(h8*)&qr1;

    // group 0
    {
        float2 h0 = __half22float2(__hmax2(__hadd2(p0.a, q0.a), hz));
        float2 h1 = __half22float2(__hmax2(__hadd2(p0.b, q0.b), hz));
        float2 h2 = __half22float2(__hmax2(__hadd2(p0.c, q0.c), hz));
        float2 h3 = __half22float2(__hmax2(__hadd2(p0.d, q0.d), hz));
        float s = h0.x * w0.x + h0.y * w0.y + h1.x * w0.z + h1.y * w0.w
                + h2.x * w1.x + h2.y * w1.y + h3.x * w1.z + h3.y * w1.w;
        s += __shfl_xor_sync(0xFFFFFFFFu, s, 4);
        s += __shfl_xor_sync(0xFFFFFFFFu, s, 2);
        s += __shfl_xor_sync(0xFFFFFFFFu, s, 1);
        if (cid == 0 && v0) out[e0] = s + bias;
    }
    // group 1
    {
        float2 h0 = __half22float2(__hmax2(__hadd2(p1.a, q1.a), hz));
        float2 h1 = __half22float2(__hmax2(__hadd2(p1.b, q1.b), hz));
        float2 h2 = __half22float2(__hmax2(__hadd2(p1.c, q1.c), hz));
        float2 h3 = __half22float2(__hmax2(__hadd2(p1.d, q1.d), hz));
        float s = h0.x * w0.x + h0.y * w0.y + h1.x * w0.z + h1.y * w0.w
                + h2.x * w1.x + h2.y * w1.y + h3.x * w1.z + h3.y * w1.w;
        s += __shfl_xor_sync(0xFFFFFFFFu, s, 4);
        s += __shfl_xor_sync(0xFFFFFFFFu, s, 2);
        s += __shfl_xor_sync(0xFFFFFFFFu, s, 1);
        if (cid == 0 && v1) out[e1] = s + bias;
    }
}

// ---------------------------------------------------------------------------
extern "C" void kernel_launch(void* const* d_in, const int* in_sizes, int n_in,
                              void* d_out, int out_size) {
    const float* x    = (const float*)d_in[0];
    const int*   ei   = (const int*)d_in[1];
    const float* Wenc = (const float*)d_in[2];
    const float* benc = (const float*)d_in[3];
    const float* W1   = (const float*)d_in[4];
    const float* b1   = (const float*)d_in[5];
    const float* W2   = (const float*)d_in[6];
    const float* b2   = (const float*)d_in[7];
    float* out = (float*)d_out;

    int N = in_sizes[0] / DD;          // 50000
    int E = in_sizes[1] / 2;           // 800000

    int n4 = N * DD / 4;
    k_prep<<<(n4 + 255) / 256, 256>>>(x, ei, n4);

    {
        long long warps = ((long long)E + 1) / 2;
        long long threads = warps * 32;
        int blocks = (int)((threads + 255) / 256);
        k_scatter<<<blocks, 256>>>(ei, E);
    }

    {
        int smem_bytes = NODE_SMEM_FLOATS * (int)sizeof(float);
        cudaFuncSetAttribute(k_node, cudaFuncAttributeMaxDynamicSharedMemorySize, smem_bytes);
        int blocks = (N + TILE_M - 1) / TILE_M;
        k_node<<<blocks, NODE_TPB, smem_bytes>>>(Wenc, benc, W1, b1, N);
    }

    {
        long long warps = ((long long)E + 7) / 8;
        long long threads = warps * 32;
        int blocks = (int)((threads + 255) / 256);
        k_edge<<<blocks, 256>>>(ei, W2, b2, out, E);
    }
}

// round 7
// speedup vs baseline: 2.2080x; 1.0319x over previous
#include <cuda_runtime.h>
#include <cuda_fp16.h>
#include <cstdint>

#define DD 64
#define MAXN 50000

// scratch (static __device__ — no allocations allowed)
__device__ float  g_in[MAXN * DD];    // x pre-filled, scatter adds -> In = x + agg
__device__ __half g_xh[MAXN * DD];    // fp16 copy of x (scatter read source)
__device__ __half g_P[MAXN * DD];     // fp16 node_emb @ W1a
__device__ __half g_Q[MAXN * DD];     // fp16 node_emb @ W1b + b1 (bias folded)
__device__ int    g_shift;            // 0 = int32 edge_index, 1 = int64

struct alignas(16) h8 { __half2 a, b, c, d; };
struct alignas(8)  h4 { __half2 a, b; };

// ---------------------------------------------------------------------------
// Copy/convert + dtype probe: g_in = x; g_xh = half(x).
// (int64 with idx<50000 -> every odd 32-bit word == 0)
// ---------------------------------------------------------------------------
__global__ void k_prep(const float* __restrict__ x, const int* __restrict__ ei, int n4) {
    int i = blockIdx.x * blockDim.x + threadIdx.x;
    if (i < n4) {
        float4 v = ((const float4*)x)[i];
        ((float4*)g_in)[i] = v;
        h4 h;
        h.a = __floats2half2_rn(v.x, v.y);
        h.b = __floats2half2_rn(v.z, v.w);
        ((h4*)g_xh)[i] = h;
    }
    if (i == 0) {
        int z = 0;
#pragma unroll
        for (int k = 1; k < 32; k += 2) z |= ei[k];
        g_shift = (z == 0) ? 1 : 0;
    }
}

// ---------------------------------------------------------------------------
// Scatter: In[dst] += x[src]. 4 edges/warp, 2 edges per half-warp (serial),
// 16 lanes/edge. Indices loaded cooperatively (8 words/warp) + shuffled.
// ---------------------------------------------------------------------------
__global__ void k_scatter(const int* __restrict__ ei, int E) {
    int shift = g_shift;
    int t = blockIdx.x * blockDim.x + threadIdx.x;
    int warp = t >> 5;
    int lane = t & 31;
    long long base = (long long)warp * 4;

    // lanes (mod 8): 0..3 -> src[base+li], 4..7 -> dst[base+li]
    int l  = lane & 7;
    int li = l & 3;
    long long pos = (l < 4) ? (base + li) : ((long long)E + base + li);
    int myidx = 0;
    if (base + li < E) myidx = ((const int*)ei)[pos << shift];

    const unsigned FULL = 0xFFFFFFFFu;
    int half = lane >> 4;        // 0..1
    int sub  = lane & 15;        // float4 chunk within row
    int sA = __shfl_sync(FULL, myidx, half);
    int sB = __shfl_sync(FULL, myidx, 2 + half);
    int dA = __shfl_sync(FULL, myidx, 4 + half);
    int dB = __shfl_sync(FULL, myidx, 6 + half);
    bool vA = (base + half) < E;
    bool vB = (base + 2 + half) < E;

    float2 rA = make_float2(0.f, 0.f), rB = make_float2(0.f, 0.f);
    if (vA) rA = __ldcs((const float2*)(g_xh + (size_t)sA * 64) + sub);
    if (vB) rB = __ldcs((const float2*)(g_xh + (size_t)sB * 64) + sub);

    if (vA) {
        h4 hv = *(h4*)&rA;
        float2 f0 = __half22float2(hv.a);
        float2 f1 = __half22float2(hv.b);
        atomicAdd((float4*)(g_in + (size_t)dA * 64) + sub,
                  make_float4(f0.x, f0.y, f1.x, f1.y));
    }
    if (vB) {
        h4 hv = *(h4*)&rB;
        float2 f0 = __half22float2(hv.a);
        float2 f1 = __half22float2(hv.b);
        atomicAdd((float4*)(g_in + (size_t)dB * 64) + sub,
                  make_float4(f0.x, f0.y, f1.x, f1.y));
    }
}

// ---------------------------------------------------------------------------
// Node kernel: register-tiled chained GEMM, fp16 epilogue.
// Block = 32 nodes, 256 threads.
//   phase1: emb = relu(In @ Wenc + be)        thread tile 2x4
//   phase2: [P|Q] = emb @ [W1a|W1b] (+b1->Q)  thread tile 2x8, store half
// ---------------------------------------------------------------------------
#define TILE_M 32
#define NODE_TPB 256
#define ST 36
#define NODE_SMEM_FLOATS (2304 + 4096 + 8192 + 64 + 64)

__global__ void __launch_bounds__(NODE_TPB, 3)
k_node(const float* __restrict__ Wenc, const float* __restrict__ benc,
       const float* __restrict__ W1, const float* __restrict__ b1, int N) {
    extern __shared__ float sm[];
    float* sInT = sm;            // 2304: [k][m] stride 36
    float* sWe  = sm + 2304;     // 4096: [k][64]
    float* sW1  = sm + 6400;     // 8192: [k][128] (0..63 = W1a, 64..127 = W1b)
    float* sBe  = sm + 14592;    // 64
    float* sB1  = sm + 14656;    // 64

    int tid = threadIdx.x;
    int node0 = blockIdx.x * TILE_M;

    for (int i = tid; i < 4096; i += NODE_TPB) sWe[i] = Wenc[i];
    for (int i = tid; i < 8192; i += NODE_TPB) {
        int part = i >> 12;
        int rem  = i & 4095;
        int k    = rem >> 6;
        int j    = rem & 63;
        sW1[k * 128 + part * 64 + j] = W1[i];
    }
    if (tid < 64) { sBe[tid] = benc[tid]; sB1[tid] = b1[tid]; }

    {
        const float4* in4 = (const float4*)g_in;
#pragma unroll
        for (int it = 0; it < 2; it++) {
            int t = tid + it * NODE_TPB;
            int c = t & 15;
            int r = t >> 4;
            int node = node0 + r;
            float4 s = make_float4(0.f, 0.f, 0.f, 0.f);
            if (node < N) s = in4[(size_t)node * 16 + c];
            sInT[(4 * c + 0) * ST + r] = s.x;
            sInT[(4 * c + 1) * ST + r] = s.y;
            sInT[(4 * c + 2) * ST + r] = s.z;
            sInT[(4 * c + 3) * ST + r] = s.w;
        }
    }
    __syncthreads();

    int tm = tid & 15;
    int tn = tid >> 4;

    // ---- phase 1 ----
    float c1[2][4];
#pragma unroll
    for (int i = 0; i < 4; i++) { c1[0][i] = 0.f; c1[1][i] = 0.f; }
#pragma unroll 16
    for (int k = 0; k < 64; k++) {
        float2 a = *(const float2*)&sInT[k * ST + 2 * tm];
        float4 b = *(const float4*)&sWe[k * 64 + 4 * tn];
        c1[0][0] += a.x * b.x; c1[0][1] += a.x * b.y;
        c1[0][2] += a.x * b.z; c1[0][3] += a.x * b.w;
        c1[1][0] += a.y * b.x; c1[1][1] += a.y * b.y;
        c1[1][2] += a.y * b.z; c1[1][3] += a.y * b.w;
    }
    __syncthreads();
#pragma unroll
    for (int i = 0; i < 4; i++) {
        float bb = sBe[4 * tn + i];
        sInT[(4 * tn + i) * ST + 2 * tm]     = fmaxf(c1[0][i] + bb, 0.f);
        sInT[(4 * tn + i) * ST + 2 * tm + 1] = fmaxf(c1[1][i] + bb, 0.f);
    }
    __syncthreads();

    // ---- phase 2 ----
    float c2[2][8];
#pragma unroll
    for (int i = 0; i < 8; i++) { c2[0][i] = 0.f; c2[1][i] = 0.f; }
#pragma unroll 8
    for (int k = 0; k < 64; k++) {
        float2 a   = *(const float2*)&sInT[k * ST + 2 * tm];
        float4 b0  = *(const float4*)&sW1[k * 128 + 8 * tn];
        float4 b1v = *(const float4*)&sW1[k * 128 + 8 * tn + 4];
        c2[0][0] += a.x * b0.x;  c2[0][1] += a.x * b0.y;
        c2[0][2] += a.x * b0.z;  c2[0][3] += a.x * b0.w;
        c2[0][4] += a.x * b1v.x; c2[0][5] += a.x * b1v.y;
        c2[0][6] += a.x * b1v.z; c2[0][7] += a.x * b1v.w;
        c2[1][0] += a.y * b0.x;  c2[1][1] += a.y * b0.y;
        c2[1][2] += a.y * b0.z;  c2[1][3] += a.y * b0.w;
        c2[1][4] += a.y * b1v.x; c2[1][5] += a.y * b1v.y;
        c2[1][6] += a.y * b1v.z; c2[1][7] += a.y * b1v.w;
    }

    // ---- epilogue ----
#pragma unroll
    for (int r = 0; r < 2; r++) {
        int node = node0 + 2 * tm + r;
        if (node >= N) continue;
        if (tn < 8) {
            h8 v;
            v.a = __floats2half2_rn(c2[r][0], c2[r][1]);
            v.b = __floats2half2_rn(c2[r][2], c2[r][3]);
            v.c = __floats2half2_rn(c2[r][4], c2[r][5]);
            v.d = __floats2half2_rn(c2[r][6], c2[r][7]);
            *(h8*)(g_P + (size_t)node * 64 + 8 * tn) = v;
        } else {
            int j = 8 * (tn - 8);
            h8 v;
            v.a = __floats2half2_rn(c2[r][0] + sB1[j + 0], c2[r][1] + sB1[j + 1]);
            v.b = __floats2half2_rn(c2[r][2] + sB1[j + 2], c2[r][3] + sB1[j + 3]);
            v.c = __floats2half2_rn(c2[r][4] + sB1[j + 4], c2[r][5] + sB1[j + 5]);
            v.d = __floats2half2_rn(c2[r][6] + sB1[j + 6], c2[r][7] + sB1[j + 7]);
            *(h8*)(g_Q + (size_t)node * 64 + j) = v;
        }
    }
}

// ---------------------------------------------------------------------------
// Edge kernel: 8 edges/warp (2 per 8-lane group), fp16 rows, streaming loads.
// Indices loaded cooperatively (16 words/warp by lanes 0..15) + shuffled.
//   out[e] = relu(P[src] + Q[dst]) . W2 + b2
// ---------------------------------------------------------------------------
__global__ void k_edge(const int* __restrict__ ei, const float* __restrict__ W2,
                       const float* __restrict__ b2, float* __restrict__ out, int E) {
    int shift = g_shift;
    int t = blockIdx.x * blockDim.x + threadIdx.x;
    int warp = t >> 5;
    int lane = t & 31;
    int esub = lane >> 3;      // 0..3
    int cid  = lane & 7;       // 0..7
    long long base = (long long)warp * 8;

    // lanes (mod 16): 0..7 -> src[base+li], 8..15 -> dst[base+li]
    int l  = lane & 15;
    int li = l & 7;
    long long pos = (l < 8) ? (base + li) : ((long long)E + base + li);
    int myidx = 0;
    if (base + li < E) myidx = ei[pos << shift];

    const unsigned FULL = 0xFFFFFFFFu;
    int s0 = __shfl_sync(FULL, myidx, esub);
    int s1 = __shfl_sync(FULL, myidx, esub + 4);
    int d0 = __shfl_sync(FULL, myidx, 8 + esub);
    int d1 = __shfl_sync(FULL, myidx, 12 + esub);

    long long e0 = base + esub;
    long long e1 = e0 + 4;
    bool v0 = e0 < E, v1 = e1 < E;

    const float4* Pf = (const float4*)g_P;
    const float4* Qf = (const float4*)g_Q;
    float4 pr0 = __ldcs(Pf + (size_t)s0 * 8 + cid);
    float4 qr0 = __ldcs(Qf + (size_t)d0 * 8 + cid);
    float4 pr1 = __ldcs(Pf + (size_t)s1 * 8 + cid);
    float4 qr1 = __ldcs(Qf + (size_t)d1 * 8 + cid);

    float4 w0 = __ldg((const float4*)W2 + 2 * cid);
    float4 w1 = __ldg((const float4*)W2 + 2 * cid + 1);
    float bias = __ldg(b2);
    const __half2 hz = __float2half2_rn(0.f);

    h8 p0 = *(h8*)&pr0, q0 = *(h8*)&qr0;
    h8 p1 = *(h8*)&pr1, q1 = *(h8*)&qr1;

    // group 0
    {
        float2 h0 = __half22float2(__hmax2(__hadd2(p0.a, q0.a), hz));
        float2 h1 = __half22float2(__hmax2(__hadd2(p0.b, q0.b), hz));
        float2 h2 = __half22float2(__hmax2(__hadd2(p0.c, q0.c), hz));
        float2 h3 = __half22float2(__hmax2(__hadd2(p0.d, q0.d), hz));
        float s = h0.x * w0.x + h0.y * w0.y + h1.x * w0.z + h1.y * w0.w
                + h2.x * w1.x + h2.y * w1.y + h3.x * w1.z + h3.y * w1.w;
        s += __shfl_xor_sync(FULL, s, 4);
        s += __shfl_xor_sync(FULL, s, 2);
        s += __shfl_xor_sync(FULL, s, 1);
        if (cid == 0 && v0) out[e0] = s + bias;
    }
    // group 1
    {
        float2 h0 = __half22float2(__hmax2(__hadd2(p1.a, q1.a), hz));
        float2 h1 = __half22float2(__hmax2(__hadd2(p1.b, q1.b), hz));
        float2 h2 = __half22float2(__hmax2(__hadd2(p1.c, q1.c), hz));
        float2 h3 = __half22float2(__hmax2(__hadd2(p1.d, q1.d), hz));
        float s = h0.x * w0.x + h0.y * w0.y + h1.x * w0.z + h1.y * w0.w
                + h2.x * w1.x + h2.y * w1.y + h3.x * w1.z + h3.y * w1.w;
        s += __shfl_xor_sync(FULL, s, 4);
        s += __shfl_xor_sync(FULL, s, 2);
        s += __shfl_xor_sync(FULL, s, 1);
        if (cid == 0 && v1) out[e1] = s + bias;
    }
}

// ---------------------------------------------------------------------------
extern "C" void kernel_launch(void* const* d_in, const int* in_sizes, int n_in,
                              void* d_out, int out_size) {
    const float* x    = (const float*)d_in[0];
    const int*   ei   = (const int*)d_in[1];
    const float* Wenc = (const float*)d_in[2];
    const float* benc = (const float*)d_in[3];
    const float* W1   = (const float*)d_in[4];
    const float* b1   = (const float*)d_in[5];
    const float* W2   = (const float*)d_in[6];
    const float* b2   = (const float*)d_in[7];
    float* out = (float*)d_out;

    int N = in_sizes[0] / DD;          // 50000
    int E = in_sizes[1] / 2;           // 800000

    int n4 = N * DD / 4;
    k_prep<<<(n4 + 255) / 256, 256>>>(x, ei, n4);

    {
        long long warps = ((long long)E + 3) / 4;
        long long threads = warps * 32;
        int blocks = (int)((threads + 255) / 256);
        k_scatter<<<blocks, 256>>>(ei, E);
    }

    {
        int smem_bytes = NODE_SMEM_FLOATS * (int)sizeof(float);
        cudaFuncSetAttribute(k_node, cudaFuncAttributeMaxDynamicSharedMemorySize, smem_bytes);
        int blocks = (N + TILE_M - 1) / TILE_M;
        k_node<<<blocks, NODE_TPB, smem_bytes>>>(Wenc, benc, W1, b1, N);
    }

    {
        long long warps = ((long long)E + 7) / 8;
        long long threads = warps * 32;
        int blocks = (int)((threads + 255) / 256);
        k_edge<<<blocks, 256>>>(ei, W2, b2, out, E);
    }
}

// round 9
// speedup vs baseline: 3.2154x; 1.4562x over previous
#include <cuda_runtime.h>
#include <cuda_fp16.h>
#include <cstdint>

#define DD 64
#define MAXN 50000

// scratch (static __device__ — no allocations allowed)
__device__ float  g_in[MAXN * DD];    // x pre-filled, scatter adds -> In = x + agg
__device__ __half g_xh[MAXN * DD];    // fp16 copy of x (scatter read source)
__device__ __half g_P[MAXN * DD];     // fp16 node_emb @ W1a
__device__ __half g_Q[MAXN * DD];     // fp16 node_emb @ W1b + b1 (bias folded)
__device__ int    g_shift;            // 0 = int32 edge_index, 1 = int64

struct alignas(16) h8 { __half2 a, b, c, d; };
struct alignas(8)  h4 { __half2 a, b; };

// ---------------------------------------------------------------------------
// Copy/convert + dtype probe: g_in = x; g_xh = half(x).
// (int64 with idx<50000 -> every odd 32-bit word == 0)
// ---------------------------------------------------------------------------
__global__ void k_prep(const float* __restrict__ x, const int* __restrict__ ei, int n4) {
    int i = blockIdx.x * blockDim.x + threadIdx.x;
    if (i < n4) {
        float4 v = ((const float4*)x)[i];
        ((float4*)g_in)[i] = v;
        h4 h;
        h.a = __floats2half2_rn(v.x, v.y);
        h.b = __floats2half2_rn(v.z, v.w);
        ((h4*)g_xh)[i] = h;
    }
    if (i == 0) {
        int z = 0;
#pragma unroll
        for (int k = 1; k < 32; k += 2) z |= ei[k];
        g_shift = (z == 0) ? 1 : 0;
    }
}

// ---------------------------------------------------------------------------
// Scatter: In[dst] += x[src]. 4 edges/warp, cooperative index load + shuffle.
// ---------------------------------------------------------------------------
__global__ void k_scatter(const int* __restrict__ ei, int E) {
    int shift = g_shift;
    int t = blockIdx.x * blockDim.x + threadIdx.x;
    int warp = t >> 5;
    int lane = t & 31;
    long long base = (long long)warp * 4;

    int l  = lane & 7;
    int li = l & 3;
    long long pos = (l < 4) ? (base + li) : ((long long)E + base + li);
    int myidx = 0;
    if (base + li < E) myidx = ((const int*)ei)[pos << shift];

    const unsigned FULL = 0xFFFFFFFFu;
    int half = lane >> 4;
    int sub  = lane & 15;
    int sA = __shfl_sync(FULL, myidx, half);
    int sB = __shfl_sync(FULL, myidx, 2 + half);
    int dA = __shfl_sync(FULL, myidx, 4 + half);
    int dB = __shfl_sync(FULL, myidx, 6 + half);
    bool vA = (base + half) < E;
    bool vB = (base + 2 + half) < E;

    float2 rA = make_float2(0.f, 0.f), rB = make_float2(0.f, 0.f);
    if (vA) rA = __ldcs((const float2*)(g_xh + (size_t)sA * 64) + sub);
    if (vB) rB = __ldcs((const float2*)(g_xh + (size_t)sB * 64) + sub);

    if (vA) {
        h4 hv = *(h4*)&rA;
        float2 f0 = __half22float2(hv.a);
        float2 f1 = __half22float2(hv.b);
        atomicAdd((float4*)(g_in + (size_t)dA * 64) + sub,
                  make_float4(f0.x, f0.y, f1.x, f1.y));
    }
    if (vB) {
        h4 hv = *(h4*)&rB;
        float2 f0 = __half22float2(hv.a);
        float2 f1 = __half22float2(hv.b);
        atomicAdd((float4*)(g_in + (size_t)dB * 64) + sub,
                  make_float4(f0.x, f0.y, f1.x, f1.y));
    }
}

// ---------------------------------------------------------------------------
// mma helpers
// ---------------------------------------------------------------------------
__device__ __forceinline__ unsigned smem_u32(const void* p) {
    return (unsigned)__cvta_generic_to_shared(p);
}
__device__ __forceinline__ void ldm_x4(unsigned addr, unsigned& a0, unsigned& a1,
                                       unsigned& a2, unsigned& a3) {
    asm volatile("ldmatrix.sync.aligned.m8n8.x4.shared.b16 {%0,%1,%2,%3}, [%4];"
                 : "=r"(a0), "=r"(a1), "=r"(a2), "=r"(a3) : "r"(addr));
}
__device__ __forceinline__ void ldm_x2t(unsigned addr, unsigned& b0, unsigned& b1) {
    asm volatile("ldmatrix.sync.aligned.m8n8.x2.trans.shared.b16 {%0,%1}, [%2];"
                 : "=r"(b0), "=r"(b1) : "r"(addr));
}
__device__ __forceinline__ void mma16816(float* c, unsigned a0, unsigned a1,
                                         unsigned a2, unsigned a3,
                                         unsigned b0, unsigned b1) {
    asm volatile(
        "mma.sync.aligned.m16n8k16.row.col.f32.f16.f16.f32 "
        "{%0,%1,%2,%3}, {%4,%5,%6,%7}, {%8,%9}, {%0,%1,%2,%3};"
        : "+f"(c[0]), "+f"(c[1]), "+f"(c[2]), "+f"(c[3])
        : "r"(a0), "r"(a1), "r"(a2), "r"(a3), "r"(b0), "r"(b1));
}

// ---------------------------------------------------------------------------
// Node kernel (tensor cores): block = 128 nodes, 8 warps.
// Warp w owns rows [16w, 16w+16).
//   phase1: emb = relu(In @ Wenc + be)   -> written back into sA (fp16)
//   phase2: [P|Q] = emb @ [W1a|W1b]      -> gmem fp16 (+b1 on Q)
// smem: sA 128x72 h | sWe 64x72 h | sW1 64x136 h | sBe 64 f | sB1 64 f
// Strides 72/136 halves = 144/272 B (16B-aligned rows, conflict-free ldmatrix).
// ---------------------------------------------------------------------------
#define NTILE_M 128
#define SA_ST 72
#define SW1_ST 136
#define NODE_SMEM_BYTES ((128 * 72 + 64 * 72 + 64 * SW1_ST) * 2 + 512)

__global__ void __launch_bounds__(256)
k_node(const float* __restrict__ Wenc, const float* __restrict__ benc,
       const float* __restrict__ W1, const float* __restrict__ b1, int N) {
    extern __shared__ __half smh[];
    __half* sA  = smh;                          // 128 x 72
    __half* sWe = smh + 128 * SA_ST;            // 64 x 72
    __half* sW1 = sWe + 64 * SA_ST;             // 64 x 136
    float*  sBe = (float*)(sW1 + 64 * SW1_ST);  // 64
    float*  sB1 = sBe + 64;                     // 64

    int tid = threadIdx.x;
    int node0 = blockIdx.x * NTILE_M;

    // stage Wenc [k][n] fp16
    for (int i = tid; i < 4096; i += 256) {
        int k = i >> 6, n = i & 63;
        sWe[k * SA_ST + n] = __float2half(Wenc[i]);
    }
    // stage W1: row (part*64+k) col j -> sW1[k][part*64+j]
    for (int i = tid; i < 8192; i += 256) {
        int part = i >> 12;
        int rem  = i & 4095;
        int k    = rem >> 6;
        int j    = rem & 63;
        sW1[k * SW1_ST + part * 64 + j] = __float2half(W1[i]);
    }
    if (tid < 64) { sBe[tid] = benc[tid]; sB1[tid] = b1[tid]; }

    // stage A = half(g_in): 128 rows x 16 float4 chunks
    {
        const float4* in4 = (const float4*)g_in;
        for (int i = tid; i < 2048; i += 256) {
            int r = i >> 4, c = i & 15;
            int node = node0 + r;
            float4 v = make_float4(0.f, 0.f, 0.f, 0.f);
            if (node < N) v = in4[(size_t)node * 16 + c];
            __half2* dst = (__half2*)&sA[r * SA_ST + c * 4];
            dst[0] = __floats2half2_rn(v.x, v.y);
            dst[1] = __floats2half2_rn(v.z, v.w);
        }
    }
    __syncthreads();

    int wid  = tid >> 5;
    int lane = tid & 31;
    int arow = 16 * wid + (lane & 15);
    int acol_off = (lane >> 4) * 8;
    int r0 = 16 * wid + (lane >> 2);
    int cb = (lane & 3) * 2;

    unsigned sA_base  = smem_u32(sA);
    unsigned sWe_base = smem_u32(sWe);
    unsigned sW1_base = smem_u32(sW1);

    // ---- phase 1: C1[16x64] = A @ Wenc ----
    float c1[8][4];
#pragma unroll
    for (int n = 0; n < 8; n++)
#pragma unroll
        for (int i = 0; i < 4; i++) c1[n][i] = 0.f;

#pragma unroll
    for (int ks = 0; ks < 4; ks++) {
        int k = ks * 16;
        unsigned a0, a1, a2, a3;
        ldm_x4(sA_base + ((arow * SA_ST + k + acol_off) << 1), a0, a1, a2, a3);
#pragma unroll
        for (int nt = 0; nt < 8; nt++) {
            unsigned b0, b1v;
            ldm_x2t(sWe_base + (((k + (lane & 15)) * SA_ST + nt * 8) << 1), b0, b1v);
            mma16816(c1[nt], a0, a1, a2, a3, b0, b1v);
        }
    }

    // epilogue 1: relu(+bias) -> sA fp16 (same rows this warp owns)
#pragma unroll
    for (int nt = 0; nt < 8; nt++) {
        int col = nt * 8 + cb;
        float be0 = sBe[col], be1 = sBe[col + 1];
        *(__half2*)&sA[r0 * SA_ST + col] =
            __floats2half2_rn(fmaxf(c1[nt][0] + be0, 0.f), fmaxf(c1[nt][1] + be1, 0.f));
        *(__half2*)&sA[(r0 + 8) * SA_ST + col] =
            __floats2half2_rn(fmaxf(c1[nt][2] + be0, 0.f), fmaxf(c1[nt][3] + be1, 0.f));
    }
    __syncwarp();

    // ---- phase 2: C2[16x128] = emb @ [W1a|W1b] ----
    float c2[16][4];
#pragma unroll
    for (int n = 0; n < 16; n++)
#pragma unroll
        for (int i = 0; i < 4; i++) c2[n][i] = 0.f;

#pragma unroll
    for (int ks = 0; ks < 4; ks++) {
        int k = ks * 16;
        unsigned a0, a1, a2, a3;
        ldm_x4(sA_base + ((arow * SA_ST + k + acol_off) << 1), a0, a1, a2, a3);
#pragma unroll
        for (int nt = 0; nt < 16; nt++) {
            unsigned b0, b1v;
            ldm_x2t(sW1_base + (((k + (lane & 15)) * SW1_ST + nt * 8) << 1), b0, b1v);
            mma16816(c2[nt], a0, a1, a2, a3, b0, b1v);
        }
    }

    // epilogue 2: nt<8 -> P, nt>=8 -> Q (+b1). half2 stores.
    int nodeA = node0 + r0;
    int nodeB = nodeA + 8;
    bool okA = nodeA < N, okB = nodeB < N;
#pragma unroll
    for (int nt = 0; nt < 8; nt++) {
        int col = nt * 8 + cb;
        if (okA) *(__half2*)&g_P[(size_t)nodeA * 64 + col] =
            __floats2half2_rn(c2[nt][0], c2[nt][1]);
        if (okB) *(__half2*)&g_P[(size_t)nodeB * 64 + col] =
            __floats2half2_rn(c2[nt][2], c2[nt][3]);
    }
#pragma unroll
    for (int nt = 8; nt < 16; nt++) {
        int col = (nt - 8) * 8 + cb;
        float b0f = sB1[col], b1f = sB1[col + 1];
        if (okA) *(__half2*)&g_Q[(size_t)nodeA * 64 + col] =
            __floats2half2_rn(c2[nt][0] + b0f, c2[nt][1] + b1f);
        if (okB) *(__half2*)&g_Q[(size_t)nodeB * 64 + col] =
            __floats2half2_rn(c2[nt][2] + b0f, c2[nt][3] + b1f);
    }
}

// ---------------------------------------------------------------------------
// Edge kernel: 8 edges/warp (2 per 8-lane group), fp16 rows, streaming loads.
//   out[e] = relu(P[src] + Q[dst]) . W2 + b2
// ---------------------------------------------------------------------------
__global__ void k_edge(const int* __restrict__ ei, const float* __restrict__ W2,
                       const float* __restrict__ b2, float* __restrict__ out, int E) {
    int shift = g_shift;
    int t = blockIdx.x * blockDim.x + threadIdx.x;
    int warp = t >> 5;
    int lane = t & 31;
    int esub = lane >> 3;
    int cid  = lane & 7;
    long long base = (long long)warp * 8;

    int l  = lane & 15;
    int li = l & 7;
    long long pos = (l < 8) ? (base + li) : ((long long)E + base + li);
    int myidx = 0;
    if (base + li < E) myidx = ei[pos << shift];

    const unsigned FULL = 0xFFFFFFFFu;
    int s0 = __shfl_sync(FULL, myidx, esub);
    int s1 = __shfl_sync(FULL, myidx, esub + 4);
    int d0 = __shfl_sync(FULL, myidx, 8 + esub);
    int d1 = __shfl_sync(FULL, myidx, 12 + esub);

    long long e0 = base + esub;
    long long e1 = e0 + 4;
    bool v0 = e0 < E, v1 = e1 < E;

    const float4* Pf = (const float4*)g_P;
    const float4* Qf = (const float4*)g_Q;
    float4 pr0 = __ldcs(Pf + (size_t)s0 * 8 + cid);
    float4 qr0 = __ldcs(Qf + (size_t)d0 * 8 + cid);
    float4 pr1 = __ldcs(Pf + (size_t)s1 * 8 + cid);
    float4 qr1 = __ldcs(Qf + (size_t)d1 * 8 + cid);

    float4 w0 = __ldg((const float4*)W2 + 2 * cid);
    float4 w1 = __ldg((const float4*)W2 + 2 * cid + 1);
    float bias = __ldg(b2);
    const __half2 hz = __float2half2_rn(0.f);

    h8 p0 = *(h8*)&pr0, q0 = *(h8*)&qr0;
    h8 p1 = *(h8*)&pr1, q1 = *(h8*)&qr1;

    {
        float2 h0 = __half22float2(__hmax2(__hadd2(p0.a, q0.a), hz));
        float2 h1 = __half22float2(__hmax2(__hadd2(p0.b, q0.b), hz));
        float2 h2 = __half22float2(__hmax2(__hadd2(p0.c, q0.c), hz));
        float2 h3 = __half22float2(__hmax2(__hadd2(p0.d, q0.d), hz));
        float s = h0.x * w0.x + h0.y * w0.y + h1.x * w0.z + h1.y * w0.w
                + h2.x * w1.x + h2.y * w1.y + h3.x * w1.z + h3.y * w1.w;
        s += __shfl_xor_sync(FULL, s, 4);
        s += __shfl_xor_sync(FULL, s, 2);
        s += __shfl_xor_sync(FULL, s, 1);
        if (cid == 0 && v0) out[e0] = s + bias;
    }
    {
        float2 h0 = __half22float2(__hmax2(__hadd2(p1.a, q1.a), hz));
        float2 h1 = __half22float2(__hmax2(__hadd2(p1.b, q1.b), hz));
        float2 h2 = __half22float2(__hmax2(__hadd2(p1.c, q1.c), hz));
        float2 h3 = __half22float2(__hmax2(__hadd2(p1.d, q1.d), hz));
        float s = h0.x * w0.x + h0.y * w0.y + h1.x * w0.z + h1.y * w0.w
                + h2.x * w1.x + h2.y * w1.y + h3.x * w1.z + h3.y * w1.w;
        s += __shfl_xor_sync(FULL, s, 4);
        s += __shfl_xor_sync(FULL, s, 2);
        s += __shfl_xor_sync(FULL, s, 1);
        if (cid == 0 && v1) out[e1] = s + bias;
    }
}

// ---------------------------------------------------------------------------
extern "C" void kernel_launch(void* const* d_in, const int* in_sizes, int n_in,
                              void* d_out, int out_size) {
    const float* x    = (const float*)d_in[0];
    const int*   ei   = (const int*)d_in[1];
    const float* Wenc = (const float*)d_in[2];
    const float* benc = (const float*)d_in[3];
    const float* W1   = (const float*)d_in[4];
    const float* b1   = (const float*)d_in[5];
    const float* W2   = (const float*)d_in[6];
    const float* b2   = (const float*)d_in[7];
    float* out = (float*)d_out;

    int N = in_sizes[0] / DD;          // 50000
    int E = in_sizes[1] / 2;           // 800000

    int n4 = N * DD / 4;
    k_prep<<<(n4 + 255) / 256, 256>>>(x, ei, n4);

    {
        long long warps = ((long long)E + 3) / 4;
        long long threads = warps * 32;
        int blocks = (int)((threads + 255) / 256);
        k_scatter<<<blocks, 256>>>(ei, E);
    }

    {
        int blocks = (N + NTILE_M - 1) / NTILE_M;
        k_node<<<blocks, 256, NODE_SMEM_BYTES>>>(Wenc, benc, W1, b1, N);
    }

    {
        long long warps = ((long long)E + 7) / 8;
        long long threads = warps * 32;
        int blocks = (int)((threads + 255) / 256);
        k_edge<<<blocks, 256>>>(ei, W2, b2, out, E);
    }
}